// round 2
// baseline (speedup 1.0000x reference)
#include <cuda_runtime.h>
#include <cuda_bf16.h>

// ---------------------------------------------------------------------------
// Problem constants
// ---------------------------------------------------------------------------
constexpr int BATCH  = 128;
constexpr int NPTS   = 65536;
constexpr int NPT    = 10;     // NPOINT
constexpr int NS     = 8;      // NSAMPLE
constexpr int NPOS   = BATCH * NPT * NS;  // 10240 positions through the conv stack

constexpr int FPS_T  = 1024;
constexpr int PPT    = NPTS / FPS_T;      // 64 points per thread

constexpr int TT     = 512;               // tail kernel threads
constexpr int TPOS   = NPOS / TT;         // 20 positions per tail thread

// ---------------------------------------------------------------------------
// Device scratch (no allocations allowed)
// ---------------------------------------------------------------------------
__device__ float g_newxyz[BATCH * NPT * 3];   // FPS centroids
__device__ float g_grouped[NPOS * 3];         // relative coords [b][s][k][c]
__device__ float g_act1[NPOS * 8];            // layer1 activations
__device__ float g_act2[NPOS * 8];            // layer2 activations
__device__ float g_act3[NPOS * 16];           // layer3 pre/post-BN
__device__ float g_feat[BATCH * 160];         // maxpooled features
__device__ float g_h[BATCH * 128];            // fc1 activations

// ---------------------------------------------------------------------------
// Kernel 1: Farthest point sampling. One CTA per batch, coalesced interleave:
// thread t owns points n = t + i*1024. dist[] in per-thread local memory.
// Arithmetic is explicitly unfused and identical to the verified version.
// ---------------------------------------------------------------------------
__global__ void __launch_bounds__(FPS_T, 1) fps_kernel(const float* __restrict__ pc) {
    const int b = blockIdx.x;
    const int t = threadIdx.x;
    const int lane = t & 31, wid = t >> 5;
    const float* __restrict__ px = pc + (size_t)b * 3 * NPTS;
    const float* __restrict__ py = px + NPTS;
    const float* __restrict__ pz = px + 2 * NPTS;

    __shared__ float s_c[3];
    __shared__ float s_wval[32];
    __shared__ int   s_widx[32];

    float dist[PPT];                     // local memory (dynamic indexing)
    for (int i = 0; i < PPT; i++) dist[i] = 1e10f;

    if (t == 0) {
        float cx = px[0], cy = py[0], cz = pz[0];
        s_c[0] = cx; s_c[1] = cy; s_c[2] = cz;
        float* o = &g_newxyz[b * NPT * 3];
        o[0] = cx; o[1] = cy; o[2] = cz;
    }
    __syncthreads();

    for (int it = 1; it < NPT; ++it) {
        const float cx = s_c[0], cy = s_c[1], cz = s_c[2];
        float bv = -1e30f;
        int   bi = 0;
        #pragma unroll 8
        for (int i = 0; i < PPT; i++) {
            int n = t + i * FPS_T;                       // coalesced
            float dx = __fadd_rn(px[n], -cx);
            float dy = __fadd_rn(py[n], -cy);
            float dz = __fadd_rn(pz[n], -cz);
            float d  = __fadd_rn(__fadd_rn(__fmul_rn(dx, dx), __fmul_rn(dy, dy)),
                                 __fmul_rn(dz, dz));
            float dd = fminf(dist[i], d);
            dist[i] = dd;
            if (dd > bv) { bv = dd; bi = n; }            // i ascending -> first max
        }
        // warp argmax (min-index tie-break)
        #pragma unroll
        for (int off = 16; off > 0; off >>= 1) {
            float ov = __shfl_down_sync(0xFFFFFFFFu, bv, off);
            int   oi = __shfl_down_sync(0xFFFFFFFFu, bi, off);
            if (ov > bv || (ov == bv && oi < bi)) { bv = ov; bi = oi; }
        }
        if (lane == 0) { s_wval[wid] = bv; s_widx[wid] = bi; }
        __syncthreads();
        if (t < 32) {
            bv = s_wval[t]; bi = s_widx[t];
            #pragma unroll
            for (int off = 16; off > 0; off >>= 1) {
                float ov = __shfl_down_sync(0xFFFFFFFFu, bv, off);
                int   oi = __shfl_down_sync(0xFFFFFFFFu, bi, off);
                if (ov > bv || (ov == bv && oi < bi)) { bv = ov; bi = oi; }
            }
            if (t == 0) {
                int fi = bi;
                float cx2 = px[fi], cy2 = py[fi], cz2 = pz[fi];
                s_c[0] = cx2; s_c[1] = cy2; s_c[2] = cz2;
                float* o = &g_newxyz[(b * NPT + it) * 3];
                o[0] = cx2; o[1] = cy2; o[2] = cz2;
            }
        }
        __syncthreads();
    }
}

// ---------------------------------------------------------------------------
// Kernel 2: ball query + grouping. One warp per (batch, centroid).
// ---------------------------------------------------------------------------
__global__ void ballquery_kernel(const float* __restrict__ pc) {
    int wid  = (blockIdx.x * blockDim.x + threadIdx.x) >> 5;
    int lane = threadIdx.x & 31;
    if (wid >= BATCH * NPT) return;
    int b = wid / NPT;

    const float* __restrict__ px = pc + (size_t)b * 3 * NPTS;
    const float* __restrict__ py = px + NPTS;
    const float* __restrict__ pz = px + 2 * NPTS;
    const float* c = &g_newxyz[wid * 3];
    const float cx = c[0], cy = c[1], cz = c[2];
    const float cn2 = __fadd_rn(__fadd_rn(__fmul_rn(cx, cx), __fmul_rn(cy, cy)),
                                __fmul_rn(cz, cz));
    const float R2 = 0.04f;

    int found = 0;
    int idxs[NS];
    for (int base = 0; base < NPTS && found < NS; base += 32) {
        int n = base + lane;
        float x = px[n], y = py[n], z = pz[n];
        float pn2 = __fadd_rn(__fadd_rn(__fmul_rn(x, x), __fmul_rn(y, y)),
                              __fmul_rn(z, z));
        float dot = __fadd_rn(__fadd_rn(__fmul_rn(cx, x), __fmul_rn(cy, y)),
                              __fmul_rn(cz, z));
        float sq  = __fadd_rn(__fadd_rn(cn2, pn2), -__fmul_rn(2.0f, dot));
        unsigned m = __ballot_sync(0xFFFFFFFFu, sq <= R2);
        while (m && found < NS) {
            int l = __ffs(m) - 1;
            m &= m - 1;
            idxs[found++] = base + l;
        }
    }
    for (int k = found; k < NS; k++) idxs[k] = idxs[0];

    if (lane < NS) {
        int n = idxs[lane];
        float* o = &g_grouped[(wid * NS + lane) * 3];
        o[0] = __fadd_rn(px[n], -cx);
        o[1] = __fadd_rn(py[n], -cy);
        o[2] = __fadd_rn(pz[n], -cz);
    }
}

// ---------------------------------------------------------------------------
// Tail kernel: layers 1-3 + BN + relu + maxpool + fc1 + BN + relu + fc2.
// ONE CTA of 512 threads; all cross-thread state via global scratch (L1/L2
// hot) and shared-memory stats. Deterministic double-precision reductions.
// ---------------------------------------------------------------------------
__shared__ double s_red[16 * 16];   // [warp][16]
__shared__ float  s_sc[16], s_sh[16];
__shared__ float  s_fsc[128], s_fsh[128];

// reduce 16 per-thread doubles across the CTA; result in s_red[0..15]
__device__ __forceinline__ void block_reduce16(double* v) {
    const int t = threadIdx.x, lane = t & 31, w = t >> 5;
    #pragma unroll
    for (int off = 16; off > 0; off >>= 1) {
        #pragma unroll
        for (int k = 0; k < 16; k++)
            v[k] += __shfl_down_sync(0xFFFFFFFFu, v[k], off);
    }
    if (lane == 0) {
        #pragma unroll
        for (int k = 0; k < 16; k++) s_red[w * 16 + k] = v[k];
    }
    __syncthreads();
    if (t < 16) {
        double a = 0.0;
        #pragma unroll
        for (int ww = 0; ww < TT / 32; ww++) a += s_red[ww * 16 + t];
        s_red[t] = a;
    }
    __syncthreads();
}

__global__ void __launch_bounds__(TT) tail_kernel(
    const float* __restrict__ w1, const float* __restrict__ b1,
    const float* __restrict__ g1, const float* __restrict__ be1,
    const float* __restrict__ w2, const float* __restrict__ b2,
    const float* __restrict__ g2, const float* __restrict__ be2,
    const float* __restrict__ w3, const float* __restrict__ b3,
    const float* __restrict__ g3, const float* __restrict__ be3,
    const float* __restrict__ fc1w, const float* __restrict__ fc1b,
    const float* __restrict__ bn1g, const float* __restrict__ bn1b,
    const float* __restrict__ fc2w, const float* __restrict__ fc2b,
    float* __restrict__ out) {
    const int t = threadIdx.x;

    // ---------------- layer 1 (3 -> 8) ----------------
    {
        double v[16];
        #pragma unroll
        for (int k = 0; k < 16; k++) v[k] = 0.0;
        for (int i = 0; i < TPOS; i++) {
            int pos = t + i * TT;
            float x0 = g_grouped[pos * 3], x1 = g_grouped[pos * 3 + 1], x2 = g_grouped[pos * 3 + 2];
            #pragma unroll
            for (int c = 0; c < 8; c++) {
                float z = w1[c * 3] * x0 + w1[c * 3 + 1] * x1 + w1[c * 3 + 2] * x2 + b1[c];
                g_act1[pos * 8 + c] = z;
                v[2 * c] += z; v[2 * c + 1] += (double)z * z;
            }
        }
        block_reduce16(v);
        if (t < 8) {
            double mean = s_red[2 * t] / NPOS;
            double var  = s_red[2 * t + 1] / NPOS - mean * mean;
            float inv = rsqrtf((float)var + 1e-5f) * g1[t];
            s_sc[t] = inv; s_sh[t] = be1[t] - (float)mean * inv;
        }
        __syncthreads();
        for (int i = 0; i < TPOS; i++) {
            int pos = t + i * TT;
            #pragma unroll
            for (int c = 0; c < 8; c++)
                g_act1[pos * 8 + c] = fmaxf(g_act1[pos * 8 + c] * s_sc[c] + s_sh[c], 0.0f);
        }
        __syncthreads();
    }

    // ---------------- layer 2 (8 -> 8) ----------------
    {
        double v[16];
        #pragma unroll
        for (int k = 0; k < 16; k++) v[k] = 0.0;
        for (int i = 0; i < TPOS; i++) {
            int pos = t + i * TT;
            float a[8];
            #pragma unroll
            for (int j = 0; j < 8; j++) a[j] = g_act1[pos * 8 + j];
            #pragma unroll
            for (int c = 0; c < 8; c++) {
                float z = b2[c];
                #pragma unroll
                for (int j = 0; j < 8; j++) z += w2[c * 8 + j] * a[j];
                g_act2[pos * 8 + c] = z;
                v[2 * c] += z; v[2 * c + 1] += (double)z * z;
            }
        }
        block_reduce16(v);
        if (t < 8) {
            double mean = s_red[2 * t] / NPOS;
            double var  = s_red[2 * t + 1] / NPOS - mean * mean;
            float inv = rsqrtf((float)var + 1e-5f) * g2[t];
            s_sc[t] = inv; s_sh[t] = be2[t] - (float)mean * inv;
        }
        __syncthreads();
        for (int i = 0; i < TPOS; i++) {
            int pos = t + i * TT;
            #pragma unroll
            for (int c = 0; c < 8; c++)
                g_act2[pos * 8 + c] = fmaxf(g_act2[pos * 8 + c] * s_sc[c] + s_sh[c], 0.0f);
        }
        __syncthreads();
    }

    // ---------------- layer 3 (8 -> 16), two half-passes ----------------
    for (int half = 0; half < 2; half++) {
        double v[16];
        #pragma unroll
        for (int k = 0; k < 16; k++) v[k] = 0.0;
        for (int i = 0; i < TPOS; i++) {
            int pos = t + i * TT;
            float a[8];
            #pragma unroll
            for (int j = 0; j < 8; j++) a[j] = g_act2[pos * 8 + j];
            #pragma unroll
            for (int c = 0; c < 8; c++) {
                int cc = half * 8 + c;
                float z = b3[cc];
                #pragma unroll
                for (int j = 0; j < 8; j++) z += w3[cc * 8 + j] * a[j];
                g_act3[pos * 16 + cc] = z;
                v[2 * c] += z; v[2 * c + 1] += (double)z * z;
            }
        }
        block_reduce16(v);
        if (t < 8) {
            int cc = half * 8 + t;
            double mean = s_red[2 * t] / NPOS;
            double var  = s_red[2 * t + 1] / NPOS - mean * mean;
            float inv = rsqrtf((float)var + 1e-5f) * g3[cc];
            s_sc[t] = inv; s_sh[t] = be3[cc] - (float)mean * inv;
        }
        __syncthreads();
        for (int i = 0; i < TPOS; i++) {
            int pos = t + i * TT;
            #pragma unroll
            for (int c = 0; c < 8; c++) {
                int cc = half * 8 + c;
                g_act3[pos * 16 + cc] = fmaxf(g_act3[pos * 16 + cc] * s_sc[c] + s_sh[c], 0.0f);
            }
        }
        __syncthreads();
    }

    // ---------------- maxpool over nsample ----------------
    for (int gidx = t; gidx < BATCH * NPT; gidx += TT) {
        int b = gidx / NPT, ss = gidx % NPT;
        #pragma unroll
        for (int c = 0; c < 16; c++) {
            float m = g_act3[(gidx * 8) * 16 + c];
            #pragma unroll
            for (int k = 1; k < 8; k++)
                m = fmaxf(m, g_act3[(gidx * 8 + k) * 16 + c]);
            g_feat[b * 160 + c * 10 + ss] = m;
        }
    }
    __syncthreads();

    // ---------------- fc1 (160 -> 128) + BN over batch + relu ----------------
    for (int j = 0; j < (BATCH * 128) / TT; j++) {
        int idx = t + j * TT;
        int b = idx >> 7, o = idx & 127;
        const float* wr = &fc1w[o * 160];
        const float* f  = &g_feat[b * 160];
        float acc = 0.0f;
        #pragma unroll
        for (int i = 0; i < 160; i++) acc += wr[i] * f[i];
        g_h[idx] = acc + fc1b[o];
    }
    __syncthreads();
    if (t < 128) {
        double s = 0.0, s2 = 0.0;
        for (int b = 0; b < BATCH; b++) {
            double x = g_h[b * 128 + t];
            s += x; s2 += x * x;
        }
        double mean = s / BATCH;
        double var  = s2 / BATCH - mean * mean;
        float inv = rsqrtf((float)var + 1e-5f) * bn1g[t];
        s_fsc[t] = inv; s_fsh[t] = bn1b[t] - (float)mean * inv;
    }
    __syncthreads();
    for (int j = 0; j < (BATCH * 128) / TT; j++) {
        int idx = t + j * TT;
        int o = idx & 127;
        g_h[idx] = fmaxf(g_h[idx] * s_fsc[o] + s_fsh[o], 0.0f);
    }
    __syncthreads();

    // ---------------- fc2 (128 -> 25) ----------------
    for (int idx = t; idx < BATCH * 25; idx += TT) {
        int b = idx / 25, o = idx % 25;
        const float* h  = &g_h[b * 128];
        const float* wr = &fc2w[o * 128];
        float acc = 0.0f;
        #pragma unroll
        for (int i = 0; i < 128; i++) acc += h[i] * wr[i];
        out[idx] = acc + fc2b[o];
    }
}

// ---------------------------------------------------------------------------
// Launch
// ---------------------------------------------------------------------------
extern "C" void kernel_launch(void* const* d_in, const int* in_sizes, int n_in,
                              void* d_out, int out_size) {
    (void)in_sizes; (void)n_in; (void)out_size;
    const float* pc    = (const float*)d_in[0];
    const float* w1    = (const float*)d_in[1];
    const float* b1    = (const float*)d_in[2];
    const float* g1    = (const float*)d_in[3];
    const float* be1   = (const float*)d_in[4];
    const float* w2    = (const float*)d_in[5];
    const float* b2    = (const float*)d_in[6];
    const float* g2    = (const float*)d_in[7];
    const float* be2   = (const float*)d_in[8];
    const float* w3    = (const float*)d_in[9];
    const float* b3    = (const float*)d_in[10];
    const float* g3    = (const float*)d_in[11];
    const float* be3   = (const float*)d_in[12];
    const float* fc1w  = (const float*)d_in[13];
    const float* fc1b  = (const float*)d_in[14];
    const float* bn1g  = (const float*)d_in[15];
    const float* bn1b  = (const float*)d_in[16];
    const float* fc2w  = (const float*)d_in[17];
    const float* fc2b  = (const float*)d_in[18];
    float* out = (float*)d_out;

    fps_kernel<<<BATCH, FPS_T>>>(pc);
    ballquery_kernel<<<(BATCH * NPT * 32 + 255) / 256, 256>>>(pc);
    tail_kernel<<<1, TT>>>(w1, b1, g1, be1, w2, b2, g2, be2, w3, b3, g3, be3,
                           fc1w, fc1b, bn1g, bn1b, fc2w, fc2b, out);
}

// round 4
// speedup vs baseline: 2.1285x; 2.1285x over previous
#include <cuda_runtime.h>
#include <cuda_bf16.h>
#include <climits>

// ---------------------------------------------------------------------------
// Problem constants
// ---------------------------------------------------------------------------
constexpr int BATCH  = 128;
constexpr int NPTS   = 65536;
constexpr int NPT    = 10;     // NPOINT
constexpr int NS     = 8;      // NSAMPLE
constexpr int NPOS   = BATCH * NPT * NS;  // 10240 positions

constexpr int FPS_T  = 1024;
constexpr int PPT    = NPTS / FPS_T;      // 64 points per thread
constexpr int CAP    = 512;               // per-centroid hit buffer capacity

constexpr int TT     = 512;               // tail kernel threads
constexpr int TPOS   = NPOS / TT;         // 20 positions per tail thread

// ---------------------------------------------------------------------------
// Device scratch (no allocations allowed)
// ---------------------------------------------------------------------------
__device__ float g_grouped[NPOS * 3];         // relative coords [b][s][k][c]
__device__ float g_act1[NPOS * 8];
__device__ float g_act2[NPOS * 8];
__device__ float g_act3[NPOS * 16];
__device__ float g_feat[BATCH * 160];
__device__ float g_h[BATCH * 128];

// ---------------------------------------------------------------------------
// Fused FPS + ball-query + grouping. One CTA of 1024 threads per batch.
// Coalesced interleave (thread t owns n = t + i*1024); dist[] in local mem
// (proven 236us @ 70% DRAM). Static shared only — no attribute changes.
// ---------------------------------------------------------------------------
__global__ void __launch_bounds__(FPS_T, 1) fps_bq_kernel(const float* __restrict__ pc) {
    const int b = blockIdx.x;
    const int t = threadIdx.x;
    const int lane = t & 31, wid = t >> 5;
    const float* __restrict__ px = pc + (size_t)b * 3 * NPTS;
    const float* __restrict__ py = px + NPTS;
    const float* __restrict__ pz = px + 2 * NPTS;

    __shared__ float s_cent[NPT * 3];
    __shared__ float s_cn2[NPT];
    __shared__ float s_wval[32];
    __shared__ int   s_widx[32];
    __shared__ int   s_cnt[NPT];
    __shared__ int   s_hits[NPT][CAP];   // 20 KB

    float dist[PPT];                     // local memory
    for (int i = 0; i < PPT; i++) dist[i] = 1e10f;

    if (t == 0) {
        s_cent[0] = px[0]; s_cent[1] = py[0]; s_cent[2] = pz[0];
    }
    __syncthreads();

    // ------------------------- FPS (9 argmax passes) -------------------------
    for (int it = 1; it < NPT; ++it) {
        const float cx = s_cent[(it - 1) * 3];
        const float cy = s_cent[(it - 1) * 3 + 1];
        const float cz = s_cent[(it - 1) * 3 + 2];
        float bv = -1e30f;
        int   bi = 0;
        #pragma unroll 8
        for (int i = 0; i < PPT; i++) {
            int n = t + i * FPS_T;                       // coalesced
            float dx = __fadd_rn(px[n], -cx);
            float dy = __fadd_rn(py[n], -cy);
            float dz = __fadd_rn(pz[n], -cz);
            float d  = __fadd_rn(__fadd_rn(__fmul_rn(dx, dx), __fmul_rn(dy, dy)),
                                 __fmul_rn(dz, dz));
            float dd = fminf(dist[i], d);
            dist[i] = dd;
            if (dd > bv) { bv = dd; bi = n; }            // i ascending -> first max
        }
        // warp argmax (min-index tie-break)
        #pragma unroll
        for (int off = 16; off > 0; off >>= 1) {
            float ov = __shfl_down_sync(0xFFFFFFFFu, bv, off);
            int   oi = __shfl_down_sync(0xFFFFFFFFu, bi, off);
            if (ov > bv || (ov == bv && oi < bi)) { bv = ov; bi = oi; }
        }
        if (lane == 0) { s_wval[wid] = bv; s_widx[wid] = bi; }
        __syncthreads();
        if (t < 32) {
            bv = s_wval[t]; bi = s_widx[t];
            #pragma unroll
            for (int off = 16; off > 0; off >>= 1) {
                float ov = __shfl_down_sync(0xFFFFFFFFu, bv, off);
                int   oi = __shfl_down_sync(0xFFFFFFFFu, bi, off);
                if (ov > bv || (ov == bv && oi < bi)) { bv = ov; bi = oi; }
            }
            if (t == 0) {
                s_cent[it * 3]     = px[bi];
                s_cent[it * 3 + 1] = py[bi];
                s_cent[it * 3 + 2] = pz[bi];
            }
        }
        __syncthreads();
    }

    // ------------------------- ball query pass -------------------------
    if (t < NPT) {
        float cx = s_cent[t * 3], cy = s_cent[t * 3 + 1], cz = s_cent[t * 3 + 2];
        s_cn2[t] = __fadd_rn(__fadd_rn(__fmul_rn(cx, cx), __fmul_rn(cy, cy)),
                             __fmul_rn(cz, cz));
        s_cnt[t] = 0;
    }
    __syncthreads();

    const float R2 = 0.04f;
    for (int i = 0; i < PPT; i++) {
        int n = t + i * FPS_T;
        float x = px[n], y = py[n], z = pz[n];
        float pn2 = __fadd_rn(__fadd_rn(__fmul_rn(x, x), __fmul_rn(y, y)),
                              __fmul_rn(z, z));
        #pragma unroll
        for (int c = 0; c < NPT; c++) {
            float cx = s_cent[c * 3], cy = s_cent[c * 3 + 1], cz = s_cent[c * 3 + 2];
            float dot = __fadd_rn(__fadd_rn(__fmul_rn(cx, x), __fmul_rn(cy, y)),
                                  __fmul_rn(cz, z));
            float sq  = __fadd_rn(__fadd_rn(s_cn2[c], pn2), -__fmul_rn(2.0f, dot));
            if (sq <= R2) {
                int p = atomicAdd(&s_cnt[c], 1);
                if (p < CAP) s_hits[c][p] = n;
            }
        }
    }
    __syncthreads();

    // ------------- select 8 smallest indices per centroid (one warp each) -------------
    if (wid < NPT) {
        const int c = wid;
        int cnt = s_cnt[c]; if (cnt > CAP) cnt = CAP;
        int mysel = INT_MAX;   // index chosen at selection step k == lane
        int first = INT_MAX;
        for (int k = 0; k < NS; k++) {
            int mymin = INT_MAX, mypos = -1;
            for (int j = lane; j < cnt; j += 32) {
                int v = s_hits[c][j];
                if (v < mymin) { mymin = v; mypos = j; }
            }
            #pragma unroll
            for (int off = 16; off > 0; off >>= 1) {
                int ov = __shfl_down_sync(0xFFFFFFFFu, mymin, off);
                int op = __shfl_down_sync(0xFFFFFFFFu, mypos, off);
                if (ov < mymin) { mymin = ov; mypos = op; }
            }
            mymin = __shfl_sync(0xFFFFFFFFu, mymin, 0);
            mypos = __shfl_sync(0xFFFFFFFFu, mypos, 0);
            if (k == 0) first = mymin;
            if (lane == k) mysel = mymin;
            if (lane == 0 && mymin != INT_MAX) s_hits[c][mypos] = INT_MAX;
            __syncwarp();
        }
        if (lane < NS) {
            int n = (mysel == INT_MAX) ? first : mysel;   // pad with first hit
            const float cx = s_cent[c * 3], cy = s_cent[c * 3 + 1], cz = s_cent[c * 3 + 2];
            float* o = &g_grouped[((b * NPT + c) * NS + lane) * 3];
            o[0] = __fadd_rn(px[n], -cx);
            o[1] = __fadd_rn(py[n], -cy);
            o[2] = __fadd_rn(pz[n], -cz);
        }
    }
}

// ---------------------------------------------------------------------------
// Tail kernel: layers 1-3 + BN + relu + maxpool + fc1 + BN + relu + fc2.
// ONE CTA of 512 threads; deterministic double-precision reductions.
// ---------------------------------------------------------------------------
__shared__ double s_red[16 * 16];
__shared__ float  s_sc[16], s_sh[16];
__shared__ float  s_fsc[128], s_fsh[128];

__device__ __forceinline__ void block_reduce16(double* v) {
    const int t = threadIdx.x, lane = t & 31, w = t >> 5;
    #pragma unroll
    for (int off = 16; off > 0; off >>= 1) {
        #pragma unroll
        for (int k = 0; k < 16; k++)
            v[k] += __shfl_down_sync(0xFFFFFFFFu, v[k], off);
    }
    if (lane == 0) {
        #pragma unroll
        for (int k = 0; k < 16; k++) s_red[w * 16 + k] = v[k];
    }
    __syncthreads();
    if (t < 16) {
        double a = 0.0;
        #pragma unroll
        for (int ww = 0; ww < TT / 32; ww++) a += s_red[ww * 16 + t];
        s_red[t] = a;
    }
    __syncthreads();
}

__global__ void __launch_bounds__(TT) tail_kernel(
    const float* __restrict__ w1, const float* __restrict__ b1,
    const float* __restrict__ g1, const float* __restrict__ be1,
    const float* __restrict__ w2, const float* __restrict__ b2,
    const float* __restrict__ g2, const float* __restrict__ be2,
    const float* __restrict__ w3, const float* __restrict__ b3,
    const float* __restrict__ g3, const float* __restrict__ be3,
    const float* __restrict__ fc1w, const float* __restrict__ fc1b,
    const float* __restrict__ bn1g, const float* __restrict__ bn1b,
    const float* __restrict__ fc2w, const float* __restrict__ fc2b,
    float* __restrict__ out) {
    const int t = threadIdx.x;

    // ---------------- layer 1 (3 -> 8) ----------------
    {
        double v[16];
        #pragma unroll
        for (int k = 0; k < 16; k++) v[k] = 0.0;
        for (int i = 0; i < TPOS; i++) {
            int pos = t + i * TT;
            float x0 = g_grouped[pos * 3], x1 = g_grouped[pos * 3 + 1], x2 = g_grouped[pos * 3 + 2];
            #pragma unroll
            for (int c = 0; c < 8; c++) {
                float z = w1[c * 3] * x0 + w1[c * 3 + 1] * x1 + w1[c * 3 + 2] * x2 + b1[c];
                g_act1[pos * 8 + c] = z;
                v[2 * c] += z; v[2 * c + 1] += (double)z * z;
            }
        }
        block_reduce16(v);
        if (t < 8) {
            double mean = s_red[2 * t] / NPOS;
            double var  = s_red[2 * t + 1] / NPOS - mean * mean;
            float inv = rsqrtf((float)var + 1e-5f) * g1[t];
            s_sc[t] = inv; s_sh[t] = be1[t] - (float)mean * inv;
        }
        __syncthreads();
        for (int i = 0; i < TPOS; i++) {
            int pos = t + i * TT;
            #pragma unroll
            for (int c = 0; c < 8; c++)
                g_act1[pos * 8 + c] = fmaxf(g_act1[pos * 8 + c] * s_sc[c] + s_sh[c], 0.0f);
        }
        __syncthreads();
    }

    // ---------------- layer 2 (8 -> 8) ----------------
    {
        double v[16];
        #pragma unroll
        for (int k = 0; k < 16; k++) v[k] = 0.0;
        for (int i = 0; i < TPOS; i++) {
            int pos = t + i * TT;
            float a[8];
            #pragma unroll
            for (int j = 0; j < 8; j++) a[j] = g_act1[pos * 8 + j];
            #pragma unroll
            for (int c = 0; c < 8; c++) {
                float z = b2[c];
                #pragma unroll
                for (int j = 0; j < 8; j++) z += w2[c * 8 + j] * a[j];
                g_act2[pos * 8 + c] = z;
                v[2 * c] += z; v[2 * c + 1] += (double)z * z;
            }
        }
        block_reduce16(v);
        if (t < 8) {
            double mean = s_red[2 * t] / NPOS;
            double var  = s_red[2 * t + 1] / NPOS - mean * mean;
            float inv = rsqrtf((float)var + 1e-5f) * g2[t];
            s_sc[t] = inv; s_sh[t] = be2[t] - (float)mean * inv;
        }
        __syncthreads();
        for (int i = 0; i < TPOS; i++) {
            int pos = t + i * TT;
            #pragma unroll
            for (int c = 0; c < 8; c++)
                g_act2[pos * 8 + c] = fmaxf(g_act2[pos * 8 + c] * s_sc[c] + s_sh[c], 0.0f);
        }
        __syncthreads();
    }

    // ---------------- layer 3 (8 -> 16), two half-passes ----------------
    for (int half = 0; half < 2; half++) {
        double v[16];
        #pragma unroll
        for (int k = 0; k < 16; k++) v[k] = 0.0;
        for (int i = 0; i < TPOS; i++) {
            int pos = t + i * TT;
            float a[8];
            #pragma unroll
            for (int j = 0; j < 8; j++) a[j] = g_act2[pos * 8 + j];
            #pragma unroll
            for (int c = 0; c < 8; c++) {
                int cc = half * 8 + c;
                float z = b3[cc];
                #pragma unroll
                for (int j = 0; j < 8; j++) z += w3[cc * 8 + j] * a[j];
                g_act3[pos * 16 + cc] = z;
                v[2 * c] += z; v[2 * c + 1] += (double)z * z;
            }
        }
        block_reduce16(v);
        if (t < 8) {
            int cc = half * 8 + t;
            double mean = s_red[2 * t] / NPOS;
            double var  = s_red[2 * t + 1] / NPOS - mean * mean;
            float inv = rsqrtf((float)var + 1e-5f) * g3[cc];
            s_sc[t] = inv; s_sh[t] = be3[cc] - (float)mean * inv;
        }
        __syncthreads();
        for (int i = 0; i < TPOS; i++) {
            int pos = t + i * TT;
            #pragma unroll
            for (int c = 0; c < 8; c++) {
                int cc = half * 8 + c;
                g_act3[pos * 16 + cc] = fmaxf(g_act3[pos * 16 + cc] * s_sc[c] + s_sh[c], 0.0f);
            }
        }
        __syncthreads();
    }

    // ---------------- maxpool over nsample ----------------
    for (int gidx = t; gidx < BATCH * NPT; gidx += TT) {
        int b = gidx / NPT, ss = gidx % NPT;
        #pragma unroll
        for (int c = 0; c < 16; c++) {
            float m = g_act3[(gidx * 8) * 16 + c];
            #pragma unroll
            for (int k = 1; k < 8; k++)
                m = fmaxf(m, g_act3[(gidx * 8 + k) * 16 + c]);
            g_feat[b * 160 + c * 10 + ss] = m;
        }
    }
    __syncthreads();

    // ---------------- fc1 (160 -> 128) + BN over batch + relu ----------------
    for (int j = 0; j < (BATCH * 128) / TT; j++) {
        int idx = t + j * TT;
        int b = idx >> 7, o = idx & 127;
        const float* wr = &fc1w[o * 160];
        const float* f  = &g_feat[b * 160];
        float acc = 0.0f;
        #pragma unroll
        for (int i = 0; i < 160; i++) acc += wr[i] * f[i];
        g_h[idx] = acc + fc1b[o];
    }
    __syncthreads();
    if (t < 128) {
        double s = 0.0, s2 = 0.0;
        for (int b = 0; b < BATCH; b++) {
            double x = g_h[b * 128 + t];
            s += x; s2 += x * x;
        }
        double mean = s / BATCH;
        double var  = s2 / BATCH - mean * mean;
        float inv = rsqrtf((float)var + 1e-5f) * bn1g[t];
        s_fsc[t] = inv; s_fsh[t] = bn1b[t] - (float)mean * inv;
    }
    __syncthreads();
    for (int j = 0; j < (BATCH * 128) / TT; j++) {
        int idx = t + j * TT;
        int o = idx & 127;
        g_h[idx] = fmaxf(g_h[idx] * s_fsc[o] + s_fsh[o], 0.0f);
    }
    __syncthreads();

    // ---------------- fc2 (128 -> 25) ----------------
    for (int idx = t; idx < BATCH * 25; idx += TT) {
        int b = idx / 25, o = idx % 25;
        const float* h  = &g_h[b * 128];
        const float* wr = &fc2w[o * 128];
        float acc = 0.0f;
        #pragma unroll
        for (int i = 0; i < 128; i++) acc += h[i] * wr[i];
        out[idx] = acc + fc2b[o];
    }
}

// ---------------------------------------------------------------------------
// Launch
// ---------------------------------------------------------------------------
extern "C" void kernel_launch(void* const* d_in, const int* in_sizes, int n_in,
                              void* d_out, int out_size) {
    (void)in_sizes; (void)n_in; (void)out_size;
    const float* pc    = (const float*)d_in[0];
    const float* w1    = (const float*)d_in[1];
    const float* b1    = (const float*)d_in[2];
    const float* g1    = (const float*)d_in[3];
    const float* be1   = (const float*)d_in[4];
    const float* w2    = (const float*)d_in[5];
    const float* b2    = (const float*)d_in[6];
    const float* g2    = (const float*)d_in[7];
    const float* be2   = (const float*)d_in[8];
    const float* w3    = (const float*)d_in[9];
    const float* b3    = (const float*)d_in[10];
    const float* g3    = (const float*)d_in[11];
    const float* be3   = (const float*)d_in[12];
    const float* fc1w  = (const float*)d_in[13];
    const float* fc1b  = (const float*)d_in[14];
    const float* bn1g  = (const float*)d_in[15];
    const float* bn1b  = (const float*)d_in[16];
    const float* fc2w  = (const float*)d_in[17];
    const float* fc2b  = (const float*)d_in[18];
    float* out = (float*)d_out;

    fps_bq_kernel<<<BATCH, FPS_T>>>(pc);
    tail_kernel<<<1, TT>>>(w1, b1, g1, be1, w2, b2, g2, be2, w3, b3, g3, be3,
                           fc1w, fc1b, bn1g, bn1b, fc2w, fc2b, out);
}

// round 6
// speedup vs baseline: 6.1364x; 2.8829x over previous
#include <cuda_runtime.h>
#include <cuda_bf16.h>
#include <climits>

// ---------------------------------------------------------------------------
// Problem constants
// ---------------------------------------------------------------------------
constexpr int BATCH  = 128;
constexpr int NPTS   = 65536;
constexpr int NPT    = 10;     // NPOINT
constexpr int NS     = 8;      // NSAMPLE
constexpr int NPOS   = BATCH * NPT * NS;  // 10240 positions

constexpr int FPS_T  = 1024;
constexpr int PPT    = NPTS / FPS_T;      // 64 points per thread
constexpr int CAP    = 512;               // per-centroid hit buffer capacity

// ---------------------------------------------------------------------------
// Device scratch (no allocations allowed)
// ---------------------------------------------------------------------------
__device__ float g_grouped[NPOS * 3];         // relative coords [b][s][k][c]
__device__ float g_act1[NPOS * 8];
__device__ float g_act2[NPOS * 8];
__device__ float g_feat[BATCH * 160];
__device__ float g_h[BATCH * 128];

// ---------------------------------------------------------------------------
// Helper: deterministic block reduction of (sum, sumsq) in double
// ---------------------------------------------------------------------------
template <int NWARP>
__device__ __forceinline__ void block_red2(double& s, double& s2, double* sm) {
    const unsigned full = 0xFFFFFFFFu;
    #pragma unroll
    for (int off = 16; off > 0; off >>= 1) {
        s  += __shfl_down_sync(full, s,  off);
        s2 += __shfl_down_sync(full, s2, off);
    }
    int w = threadIdx.x >> 5, l = threadIdx.x & 31;
    if (l == 0) { sm[w * 2] = s; sm[w * 2 + 1] = s2; }
    __syncthreads();
    if (threadIdx.x == 0) {
        double a = 0.0, b = 0.0;
        #pragma unroll
        for (int i = 0; i < NWARP; i++) { a += sm[i * 2]; b += sm[i * 2 + 1]; }
        sm[0] = a; sm[1] = b;
    }
    __syncthreads();
    s = sm[0]; s2 = sm[1];
}

// ---------------------------------------------------------------------------
// Fused FPS + ball-query + grouping. One CTA of 1024 threads per batch.
// (Verbatim the Round-4 version that passed on hardware.)
// ---------------------------------------------------------------------------
__global__ void __launch_bounds__(FPS_T, 1) fps_bq_kernel(const float* __restrict__ pc) {
    const int b = blockIdx.x;
    const int t = threadIdx.x;
    const int lane = t & 31, wid = t >> 5;
    const float* __restrict__ px = pc + (size_t)b * 3 * NPTS;
    const float* __restrict__ py = px + NPTS;
    const float* __restrict__ pz = px + 2 * NPTS;

    __shared__ float s_cent[NPT * 3];
    __shared__ float s_cn2[NPT];
    __shared__ float s_wval[32];
    __shared__ int   s_widx[32];
    __shared__ int   s_cnt[NPT];
    __shared__ int   s_hits[NPT][CAP];   // 20 KB

    float dist[PPT];                     // local memory
    for (int i = 0; i < PPT; i++) dist[i] = 1e10f;

    if (t == 0) {
        s_cent[0] = px[0]; s_cent[1] = py[0]; s_cent[2] = pz[0];
    }
    __syncthreads();

    // ------------------------- FPS (9 argmax passes) -------------------------
    for (int it = 1; it < NPT; ++it) {
        const float cx = s_cent[(it - 1) * 3];
        const float cy = s_cent[(it - 1) * 3 + 1];
        const float cz = s_cent[(it - 1) * 3 + 2];
        float bv = -1e30f;
        int   bi = 0;
        #pragma unroll 8
        for (int i = 0; i < PPT; i++) {
            int n = t + i * FPS_T;                       // coalesced
            float dx = __fadd_rn(px[n], -cx);
            float dy = __fadd_rn(py[n], -cy);
            float dz = __fadd_rn(pz[n], -cz);
            float d  = __fadd_rn(__fadd_rn(__fmul_rn(dx, dx), __fmul_rn(dy, dy)),
                                 __fmul_rn(dz, dz));
            float dd = fminf(dist[i], d);
            dist[i] = dd;
            if (dd > bv) { bv = dd; bi = n; }            // first max kept
        }
        // warp argmax (min-index tie-break)
        #pragma unroll
        for (int off = 16; off > 0; off >>= 1) {
            float ov = __shfl_down_sync(0xFFFFFFFFu, bv, off);
            int   oi = __shfl_down_sync(0xFFFFFFFFu, bi, off);
            if (ov > bv || (ov == bv && oi < bi)) { bv = ov; bi = oi; }
        }
        if (lane == 0) { s_wval[wid] = bv; s_widx[wid] = bi; }
        __syncthreads();
        if (t < 32) {
            bv = s_wval[t]; bi = s_widx[t];
            #pragma unroll
            for (int off = 16; off > 0; off >>= 1) {
                float ov = __shfl_down_sync(0xFFFFFFFFu, bv, off);
                int   oi = __shfl_down_sync(0xFFFFFFFFu, bi, off);
                if (ov > bv || (ov == bv && oi < bi)) { bv = ov; bi = oi; }
            }
            if (t == 0) {
                s_cent[it * 3]     = px[bi];
                s_cent[it * 3 + 1] = py[bi];
                s_cent[it * 3 + 2] = pz[bi];
            }
        }
        __syncthreads();
    }

    // ------------------------- ball query pass -------------------------
    if (t < NPT) {
        float cx = s_cent[t * 3], cy = s_cent[t * 3 + 1], cz = s_cent[t * 3 + 2];
        s_cn2[t] = __fadd_rn(__fadd_rn(__fmul_rn(cx, cx), __fmul_rn(cy, cy)),
                             __fmul_rn(cz, cz));
        s_cnt[t] = 0;
    }
    __syncthreads();

    const float R2 = 0.04f;
    for (int i = 0; i < PPT; i++) {
        int n = t + i * FPS_T;
        float x = px[n], y = py[n], z = pz[n];
        float pn2 = __fadd_rn(__fadd_rn(__fmul_rn(x, x), __fmul_rn(y, y)),
                              __fmul_rn(z, z));
        #pragma unroll
        for (int c = 0; c < NPT; c++) {
            float cx = s_cent[c * 3], cy = s_cent[c * 3 + 1], cz = s_cent[c * 3 + 2];
            float dot = __fadd_rn(__fadd_rn(__fmul_rn(cx, x), __fmul_rn(cy, y)),
                                  __fmul_rn(cz, z));
            float sq  = __fadd_rn(__fadd_rn(s_cn2[c], pn2), -__fmul_rn(2.0f, dot));
            if (sq <= R2) {
                int p = atomicAdd(&s_cnt[c], 1);
                if (p < CAP) s_hits[c][p] = n;
            }
        }
    }
    __syncthreads();

    // ------------- select 8 smallest indices per centroid (one warp each) -------------
    if (wid < NPT) {
        const int c = wid;
        int cnt = s_cnt[c]; if (cnt > CAP) cnt = CAP;
        int mysel = INT_MAX;   // index chosen at selection step k == lane
        int first = INT_MAX;
        for (int k = 0; k < NS; k++) {
            int mymin = INT_MAX, mypos = -1;
            for (int j = lane; j < cnt; j += 32) {
                int v = s_hits[c][j];
                if (v < mymin) { mymin = v; mypos = j; }
            }
            #pragma unroll
            for (int off = 16; off > 0; off >>= 1) {
                int ov = __shfl_down_sync(0xFFFFFFFFu, mymin, off);
                int op = __shfl_down_sync(0xFFFFFFFFu, mypos, off);
                if (ov < mymin) { mymin = ov; mypos = op; }
            }
            mymin = __shfl_sync(0xFFFFFFFFu, mymin, 0);
            mypos = __shfl_sync(0xFFFFFFFFu, mypos, 0);
            if (k == 0) first = mymin;
            if (lane == k) mysel = mymin;
            if (lane == 0 && mymin != INT_MAX) s_hits[c][mypos] = INT_MAX;
            __syncwarp();
        }
        if (lane < NS) {
            int n = (mysel == INT_MAX) ? first : mysel;   // pad with first hit
            const float cx = s_cent[c * 3], cy = s_cent[c * 3 + 1], cz = s_cent[c * 3 + 2];
            float* o = &g_grouped[((b * NPT + c) * NS + lane) * 3];
            o[0] = __fadd_rn(px[n], -cx);
            o[1] = __fadd_rn(py[n], -cy);
            o[2] = __fadd_rn(pz[n], -cz);
        }
    }
}

// ---------------------------------------------------------------------------
// Tail: Round-1 verified multi-kernel structure (one CTA per channel/feature
// -> in-block deterministic BN statistics).
// ---------------------------------------------------------------------------
__global__ void __launch_bounds__(1024) layer1_kernel(
    const float* __restrict__ w, const float* __restrict__ bias,
    const float* __restrict__ g, const float* __restrict__ be) {
    const int c = blockIdx.x, t = threadIdx.x;
    const float w0 = w[c * 3], w1 = w[c * 3 + 1], w2 = w[c * 3 + 2], bb = bias[c];
    float z[10];
    double s = 0.0, s2 = 0.0;
    #pragma unroll
    for (int i = 0; i < 10; i++) {
        int pos = t + i * 1024;
        const float* x = &g_grouped[pos * 3];
        float zz = w0 * x[0] + w1 * x[1] + w2 * x[2] + bb;
        z[i] = zz; s += zz; s2 += (double)zz * zz;
    }
    __shared__ double red[64];
    block_red2<32>(s, s2, red);
    __shared__ float s_sc, s_sh;
    if (t == 0) {
        double mean = s / NPOS;
        double var  = s2 / NPOS - mean * mean;
        float inv = rsqrtf((float)var + 1e-5f) * g[c];
        s_sc = inv; s_sh = be[c] - (float)mean * inv;
    }
    __syncthreads();
    const float sc = s_sc, sh = s_sh;
    #pragma unroll
    for (int i = 0; i < 10; i++) {
        int pos = t + i * 1024;
        g_act1[pos * 8 + c] = fmaxf(z[i] * sc + sh, 0.0f);
    }
}

__global__ void __launch_bounds__(1024) layer2_kernel(
    const float* __restrict__ w, const float* __restrict__ bias,
    const float* __restrict__ g, const float* __restrict__ be) {
    const int c = blockIdx.x, t = threadIdx.x;
    float wr[8];
    #pragma unroll
    for (int j = 0; j < 8; j++) wr[j] = w[c * 8 + j];
    const float bb = bias[c];
    float z[10];
    double s = 0.0, s2 = 0.0;
    #pragma unroll
    for (int i = 0; i < 10; i++) {
        int pos = t + i * 1024;
        const float* a = &g_act1[pos * 8];
        float zz = bb;
        #pragma unroll
        for (int j = 0; j < 8; j++) zz += wr[j] * a[j];
        z[i] = zz; s += zz; s2 += (double)zz * zz;
    }
    __shared__ double red[64];
    block_red2<32>(s, s2, red);
    __shared__ float s_sc, s_sh;
    if (t == 0) {
        double mean = s / NPOS;
        double var  = s2 / NPOS - mean * mean;
        float inv = rsqrtf((float)var + 1e-5f) * g[c];
        s_sc = inv; s_sh = be[c] - (float)mean * inv;
    }
    __syncthreads();
    const float sc = s_sc, sh = s_sh;
    #pragma unroll
    for (int i = 0; i < 10; i++) {
        int pos = t + i * 1024;
        g_act2[pos * 8 + c] = fmaxf(z[i] * sc + sh, 0.0f);
    }
}

// layer3 (8->16) fused with maxpool over nsample. One CTA per out channel (16).
__global__ void __launch_bounds__(1024) layer3_kernel(
    const float* __restrict__ w, const float* __restrict__ bias,
    const float* __restrict__ g, const float* __restrict__ be) {
    const int c = blockIdx.x, t = threadIdx.x;
    float wr[8];
    #pragma unroll
    for (int j = 0; j < 8; j++) wr[j] = w[c * 8 + j];
    const float bb = bias[c];
    float z[10];
    double s = 0.0, s2 = 0.0;
    #pragma unroll
    for (int i = 0; i < 10; i++) {
        int pos = t + i * 1024;
        const float* a = &g_act2[pos * 8];
        float zz = bb;
        #pragma unroll
        for (int j = 0; j < 8; j++) zz += wr[j] * a[j];
        z[i] = zz; s += zz; s2 += (double)zz * zz;
    }
    __shared__ double red[64];
    block_red2<32>(s, s2, red);
    __shared__ float s_sc, s_sh;
    if (t == 0) {
        double mean = s / NPOS;
        double var  = s2 / NPOS - mean * mean;
        float inv = rsqrtf((float)var + 1e-5f) * g[c];
        s_sc = inv; s_sh = be[c] - (float)mean * inv;
    }
    __syncthreads();
    const float sc = s_sc, sh = s_sh;
    __shared__ float sa[NPOS];  // 40 KB
    #pragma unroll
    for (int i = 0; i < 10; i++) {
        int pos = t + i * 1024;
        sa[pos] = fmaxf(z[i] * sc + sh, 0.0f);
    }
    __syncthreads();
    for (int gidx = t; gidx < BATCH * NPT; gidx += 1024) {
        float m = sa[gidx * 8];
        #pragma unroll
        for (int k = 1; k < 8; k++) m = fmaxf(m, sa[gidx * 8 + k]);
        int b = gidx / NPT, ss = gidx % NPT;
        g_feat[b * 160 + c * 10 + ss] = m;
    }
}

// fc1 (160->128) fused with per-feature batch-norm over B=128 + relu.
__global__ void __launch_bounds__(128) fc1_kernel(
    const float* __restrict__ w, const float* __restrict__ bias,
    const float* __restrict__ g, const float* __restrict__ be) {
    const int o = blockIdx.x, b = threadIdx.x;
    const float* wr = &w[o * 160];
    const float* f  = &g_feat[b * 160];
    float acc = 0.0f;
    #pragma unroll
    for (int i = 0; i < 160; i++) acc += wr[i] * f[i];
    const float h = acc + bias[o];

    double s = h, s2 = (double)h * h;
    __shared__ double red[8];
    block_red2<4>(s, s2, red);
    __shared__ float s_sc, s_sh;
    if (b == 0) {
        double mean = s / BATCH;
        double var  = s2 / BATCH - mean * mean;
        float inv = rsqrtf((float)var + 1e-5f) * g[o];
        s_sc = inv; s_sh = be[o] - (float)mean * inv;
    }
    __syncthreads();
    g_h[b * 128 + o] = fmaxf(h * s_sc + s_sh, 0.0f);
}

// fc2 (128->25), final output.
__global__ void fc2_kernel(const float* __restrict__ w, const float* __restrict__ bias,
                           float* __restrict__ out) {
    const int b = blockIdx.x, o = threadIdx.x;
    if (o < 25) {
        const float* h  = &g_h[b * 128];
        const float* wr = &w[o * 128];
        float acc = 0.0f;
        #pragma unroll
        for (int i = 0; i < 128; i++) acc += h[i] * wr[i];
        out[b * 25 + o] = acc + bias[o];
    }
}

// ---------------------------------------------------------------------------
// Launch
// ---------------------------------------------------------------------------
extern "C" void kernel_launch(void* const* d_in, const int* in_sizes, int n_in,
                              void* d_out, int out_size) {
    (void)in_sizes; (void)n_in; (void)out_size;
    const float* pc    = (const float*)d_in[0];
    const float* w1    = (const float*)d_in[1];
    const float* b1    = (const float*)d_in[2];
    const float* g1    = (const float*)d_in[3];
    const float* be1   = (const float*)d_in[4];
    const float* w2    = (const float*)d_in[5];
    const float* b2    = (const float*)d_in[6];
    const float* g2    = (const float*)d_in[7];
    const float* be2   = (const float*)d_in[8];
    const float* w3    = (const float*)d_in[9];
    const float* b3    = (const float*)d_in[10];
    const float* g3    = (const float*)d_in[11];
    const float* be3   = (const float*)d_in[12];
    const float* fc1w  = (const float*)d_in[13];
    const float* fc1b  = (const float*)d_in[14];
    const float* bn1g  = (const float*)d_in[15];
    const float* bn1b  = (const float*)d_in[16];
    const float* fc2w  = (const float*)d_in[17];
    const float* fc2b  = (const float*)d_in[18];
    float* out = (float*)d_out;

    fps_bq_kernel<<<BATCH, FPS_T>>>(pc);
    layer1_kernel<<<8, 1024>>>(w1, b1, g1, be1);
    layer2_kernel<<<8, 1024>>>(w2, b2, g2, be2);
    layer3_kernel<<<16, 1024>>>(w3, b3, g3, be3);
    fc1_kernel<<<128, 128>>>(fc1w, fc1b, bn1g, bn1b);
    fc2_kernel<<<128, 32>>>(fc2w, fc2b, out);
}

// round 7
// speedup vs baseline: 6.3833x; 1.0402x over previous
#include <cuda_runtime.h>
#include <cuda_bf16.h>
#include <climits>

// ---------------------------------------------------------------------------
// Problem constants
// ---------------------------------------------------------------------------
constexpr int BATCH  = 128;
constexpr int NPTS   = 65536;
constexpr int NPT    = 10;     // NPOINT
constexpr int NS     = 8;      // NSAMPLE
constexpr int NPOS   = BATCH * NPT * NS;  // 10240 positions

constexpr int FPS_T  = 1024;
constexpr int PPT    = NPTS / FPS_T;      // 64 points per thread
constexpr int CAP    = 512;               // per-centroid hit buffer capacity
constexpr int FPS_G  = 64;                // CTAs; each handles 2 batches (L2-resident)

// ---------------------------------------------------------------------------
// Device scratch (no allocations allowed)
// ---------------------------------------------------------------------------
__device__ float g_grouped[NPOS * 3];         // relative coords [b][s][k][c]
__device__ float g_act1[NPOS * 8];
__device__ float g_act2[NPOS * 8];
__device__ float g_feat[BATCH * 160];
__device__ float g_h[BATCH * 128];

// ---------------------------------------------------------------------------
// Helper: deterministic block reduction of (sum, sumsq) in double
// ---------------------------------------------------------------------------
template <int NWARP>
__device__ __forceinline__ void block_red2(double& s, double& s2, double* sm) {
    const unsigned full = 0xFFFFFFFFu;
    #pragma unroll
    for (int off = 16; off > 0; off >>= 1) {
        s  += __shfl_down_sync(full, s,  off);
        s2 += __shfl_down_sync(full, s2, off);
    }
    int w = threadIdx.x >> 5, l = threadIdx.x & 31;
    if (l == 0) { sm[w * 2] = s; sm[w * 2 + 1] = s2; }
    __syncthreads();
    if (threadIdx.x == 0) {
        double a = 0.0, b = 0.0;
        #pragma unroll
        for (int i = 0; i < NWARP; i++) { a += sm[i * 2]; b += sm[i * 2 + 1]; }
        sm[0] = a; sm[1] = b;
    }
    __syncthreads();
    s = sm[0]; s2 = sm[1];
}

// ---------------------------------------------------------------------------
// Fused FPS + ball-query + grouping. grid=64; each CTA processes batches
// blockIdx.x and blockIdx.x+64 sequentially so the concurrent working set
// (~66 MB coords+dist) stays L2-resident across the 9 argmax sweeps.
// Per-batch body is verbatim the Round-4/6 version that passed on hardware.
// ---------------------------------------------------------------------------
__global__ void __launch_bounds__(FPS_T, 1) fps_bq_kernel(const float* __restrict__ pc) {
    const int t = threadIdx.x;
    const int lane = t & 31, wid = t >> 5;

    __shared__ float s_cent[NPT * 3];
    __shared__ float s_cn2[NPT];
    __shared__ float s_wval[32];
    __shared__ int   s_widx[32];
    __shared__ int   s_cnt[NPT];
    __shared__ int   s_hits[NPT][CAP];   // 20 KB

    for (int pass = 0; pass < 2; ++pass) {
        const int b = blockIdx.x + pass * FPS_G;
        const float* __restrict__ px = pc + (size_t)b * 3 * NPTS;
        const float* __restrict__ py = px + NPTS;
        const float* __restrict__ pz = px + 2 * NPTS;

        float dist[PPT];                     // local memory
        for (int i = 0; i < PPT; i++) dist[i] = 1e10f;

        if (t == 0) {
            s_cent[0] = px[0]; s_cent[1] = py[0]; s_cent[2] = pz[0];
        }
        __syncthreads();

        // --------------------- FPS (9 argmax passes) ---------------------
        for (int it = 1; it < NPT; ++it) {
            const float cx = s_cent[(it - 1) * 3];
            const float cy = s_cent[(it - 1) * 3 + 1];
            const float cz = s_cent[(it - 1) * 3 + 2];
            float bv = -1e30f;
            int   bi = 0;
            #pragma unroll 8
            for (int i = 0; i < PPT; i++) {
                int n = t + i * FPS_T;                       // coalesced
                float dx = __fadd_rn(px[n], -cx);
                float dy = __fadd_rn(py[n], -cy);
                float dz = __fadd_rn(pz[n], -cz);
                float d  = __fadd_rn(__fadd_rn(__fmul_rn(dx, dx), __fmul_rn(dy, dy)),
                                     __fmul_rn(dz, dz));
                float dd = fminf(dist[i], d);
                dist[i] = dd;
                if (dd > bv) { bv = dd; bi = n; }            // first max kept
            }
            // warp argmax (min-index tie-break)
            #pragma unroll
            for (int off = 16; off > 0; off >>= 1) {
                float ov = __shfl_down_sync(0xFFFFFFFFu, bv, off);
                int   oi = __shfl_down_sync(0xFFFFFFFFu, bi, off);
                if (ov > bv || (ov == bv && oi < bi)) { bv = ov; bi = oi; }
            }
            if (lane == 0) { s_wval[wid] = bv; s_widx[wid] = bi; }
            __syncthreads();
            if (t < 32) {
                bv = s_wval[t]; bi = s_widx[t];
                #pragma unroll
                for (int off = 16; off > 0; off >>= 1) {
                    float ov = __shfl_down_sync(0xFFFFFFFFu, bv, off);
                    int   oi = __shfl_down_sync(0xFFFFFFFFu, bi, off);
                    if (ov > bv || (ov == bv && oi < bi)) { bv = ov; bi = oi; }
                }
                if (t == 0) {
                    s_cent[it * 3]     = px[bi];
                    s_cent[it * 3 + 1] = py[bi];
                    s_cent[it * 3 + 2] = pz[bi];
                }
            }
            __syncthreads();
        }

        // --------------------- ball query pass ---------------------
        if (t < NPT) {
            float cx = s_cent[t * 3], cy = s_cent[t * 3 + 1], cz = s_cent[t * 3 + 2];
            s_cn2[t] = __fadd_rn(__fadd_rn(__fmul_rn(cx, cx), __fmul_rn(cy, cy)),
                                 __fmul_rn(cz, cz));
            s_cnt[t] = 0;
        }
        __syncthreads();

        const float R2 = 0.04f;
        for (int i = 0; i < PPT; i++) {
            int n = t + i * FPS_T;
            float x = px[n], y = py[n], z = pz[n];
            float pn2 = __fadd_rn(__fadd_rn(__fmul_rn(x, x), __fmul_rn(y, y)),
                                  __fmul_rn(z, z));
            #pragma unroll
            for (int c = 0; c < NPT; c++) {
                float cx = s_cent[c * 3], cy = s_cent[c * 3 + 1], cz = s_cent[c * 3 + 2];
                float dot = __fadd_rn(__fadd_rn(__fmul_rn(cx, x), __fmul_rn(cy, y)),
                                      __fmul_rn(cz, z));
                float sq  = __fadd_rn(__fadd_rn(s_cn2[c], pn2), -__fmul_rn(2.0f, dot));
                if (sq <= R2) {
                    int p = atomicAdd(&s_cnt[c], 1);
                    if (p < CAP) s_hits[c][p] = n;
                }
            }
        }
        __syncthreads();

        // -------- select 8 smallest indices per centroid (one warp each) --------
        if (wid < NPT) {
            const int c = wid;
            int cnt = s_cnt[c]; if (cnt > CAP) cnt = CAP;
            int mysel = INT_MAX;   // index chosen at selection step k == lane
            int first = INT_MAX;
            for (int k = 0; k < NS; k++) {
                int mymin = INT_MAX, mypos = -1;
                for (int j = lane; j < cnt; j += 32) {
                    int v = s_hits[c][j];
                    if (v < mymin) { mymin = v; mypos = j; }
                }
                #pragma unroll
                for (int off = 16; off > 0; off >>= 1) {
                    int ov = __shfl_down_sync(0xFFFFFFFFu, mymin, off);
                    int op = __shfl_down_sync(0xFFFFFFFFu, mypos, off);
                    if (ov < mymin) { mymin = ov; mypos = op; }
                }
                mymin = __shfl_sync(0xFFFFFFFFu, mymin, 0);
                mypos = __shfl_sync(0xFFFFFFFFu, mypos, 0);
                if (k == 0) first = mymin;
                if (lane == k) mysel = mymin;
                if (lane == 0 && mymin != INT_MAX) s_hits[c][mypos] = INT_MAX;
                __syncwarp();
            }
            if (lane < NS) {
                int n = (mysel == INT_MAX) ? first : mysel;   // pad with first hit
                const float cx = s_cent[c * 3], cy = s_cent[c * 3 + 1], cz = s_cent[c * 3 + 2];
                float* o = &g_grouped[((b * NPT + c) * NS + lane) * 3];
                o[0] = __fadd_rn(px[n], -cx);
                o[1] = __fadd_rn(py[n], -cy);
                o[2] = __fadd_rn(pz[n], -cz);
            }
        }
        __syncthreads();   // protect shared buffers before next batch pass
    }
}

// ---------------------------------------------------------------------------
// Tail: one CTA per channel/feature -> in-block deterministic BN statistics.
// Per-thread partials in fp32 (reference computes stats in fp32); cross-
// thread reduction stays in double for determinism.
// ---------------------------------------------------------------------------
__global__ void __launch_bounds__(1024) layer1_kernel(
    const float* __restrict__ w, const float* __restrict__ bias,
    const float* __restrict__ g, const float* __restrict__ be) {
    const int c = blockIdx.x, t = threadIdx.x;
    const float w0 = w[c * 3], w1 = w[c * 3 + 1], w2 = w[c * 3 + 2], bb = bias[c];
    float z[10];
    float sf = 0.0f, s2f = 0.0f;
    #pragma unroll
    for (int i = 0; i < 10; i++) {
        int pos = t + i * 1024;
        const float* x = &g_grouped[pos * 3];
        float zz = w0 * x[0] + w1 * x[1] + w2 * x[2] + bb;
        z[i] = zz; sf += zz; s2f += zz * zz;
    }
    double s = sf, s2 = s2f;
    __shared__ double red[64];
    block_red2<32>(s, s2, red);
    __shared__ float s_sc, s_sh;
    if (t == 0) {
        double mean = s / NPOS;
        double var  = s2 / NPOS - mean * mean;
        float inv = rsqrtf((float)var + 1e-5f) * g[c];
        s_sc = inv; s_sh = be[c] - (float)mean * inv;
    }
    __syncthreads();
    const float sc = s_sc, sh = s_sh;
    #pragma unroll
    for (int i = 0; i < 10; i++) {
        int pos = t + i * 1024;
        g_act1[pos * 8 + c] = fmaxf(z[i] * sc + sh, 0.0f);
    }
}

__global__ void __launch_bounds__(1024) layer2_kernel(
    const float* __restrict__ w, const float* __restrict__ bias,
    const float* __restrict__ g, const float* __restrict__ be) {
    const int c = blockIdx.x, t = threadIdx.x;
    float wr[8];
    #pragma unroll
    for (int j = 0; j < 8; j++) wr[j] = w[c * 8 + j];
    const float bb = bias[c];
    float z[10];
    float sf = 0.0f, s2f = 0.0f;
    #pragma unroll
    for (int i = 0; i < 10; i++) {
        int pos = t + i * 1024;
        const float* a = &g_act1[pos * 8];
        float zz = bb;
        #pragma unroll
        for (int j = 0; j < 8; j++) zz += wr[j] * a[j];
        z[i] = zz; sf += zz; s2f += zz * zz;
    }
    double s = sf, s2 = s2f;
    __shared__ double red[64];
    block_red2<32>(s, s2, red);
    __shared__ float s_sc, s_sh;
    if (t == 0) {
        double mean = s / NPOS;
        double var  = s2 / NPOS - mean * mean;
        float inv = rsqrtf((float)var + 1e-5f) * g[c];
        s_sc = inv; s_sh = be[c] - (float)mean * inv;
    }
    __syncthreads();
    const float sc = s_sc, sh = s_sh;
    #pragma unroll
    for (int i = 0; i < 10; i++) {
        int pos = t + i * 1024;
        g_act2[pos * 8 + c] = fmaxf(z[i] * sc + sh, 0.0f);
    }
}

// layer3 (8->16) fused with maxpool over nsample. One CTA per out channel (16).
__global__ void __launch_bounds__(1024) layer3_kernel(
    const float* __restrict__ w, const float* __restrict__ bias,
    const float* __restrict__ g, const float* __restrict__ be) {
    const int c = blockIdx.x, t = threadIdx.x;
    float wr[8];
    #pragma unroll
    for (int j = 0; j < 8; j++) wr[j] = w[c * 8 + j];
    const float bb = bias[c];
    float z[10];
    float sf = 0.0f, s2f = 0.0f;
    #pragma unroll
    for (int i = 0; i < 10; i++) {
        int pos = t + i * 1024;
        const float* a = &g_act2[pos * 8];
        float zz = bb;
        #pragma unroll
        for (int j = 0; j < 8; j++) zz += wr[j] * a[j];
        z[i] = zz; sf += zz; s2f += zz * zz;
    }
    double s = sf, s2 = s2f;
    __shared__ double red[64];
    block_red2<32>(s, s2, red);
    __shared__ float s_sc, s_sh;
    if (t == 0) {
        double mean = s / NPOS;
        double var  = s2 / NPOS - mean * mean;
        float inv = rsqrtf((float)var + 1e-5f) * g[c];
        s_sc = inv; s_sh = be[c] - (float)mean * inv;
    }
    __syncthreads();
    const float sc = s_sc, sh = s_sh;
    __shared__ float sa[NPOS];  // 40 KB
    #pragma unroll
    for (int i = 0; i < 10; i++) {
        int pos = t + i * 1024;
        sa[pos] = fmaxf(z[i] * sc + sh, 0.0f);
    }
    __syncthreads();
    for (int gidx = t; gidx < BATCH * NPT; gidx += 1024) {
        float m = sa[gidx * 8];
        #pragma unroll
        for (int k = 1; k < 8; k++) m = fmaxf(m, sa[gidx * 8 + k]);
        int b = gidx / NPT, ss = gidx % NPT;
        g_feat[b * 160 + c * 10 + ss] = m;
    }
}

// fc1 (160->128) fused with per-feature batch-norm over B=128 + relu.
__global__ void __launch_bounds__(128) fc1_kernel(
    const float* __restrict__ w, const float* __restrict__ bias,
    const float* __restrict__ g, const float* __restrict__ be) {
    const int o = blockIdx.x, b = threadIdx.x;
    const float* wr = &w[o * 160];
    const float* f  = &g_feat[b * 160];
    float acc = 0.0f;
    #pragma unroll
    for (int i = 0; i < 160; i++) acc += wr[i] * f[i];
    const float h = acc + bias[o];

    double s = h, s2 = (double)h * h;
    __shared__ double red[8];
    block_red2<4>(s, s2, red);
    __shared__ float s_sc, s_sh;
    if (b == 0) {
        double mean = s / BATCH;
        double var  = s2 / BATCH - mean * mean;
        float inv = rsqrtf((float)var + 1e-5f) * g[o];
        s_sc = inv; s_sh = be[o] - (float)mean * inv;
    }
    __syncthreads();
    g_h[b * 128 + o] = fmaxf(h * s_sc + s_sh, 0.0f);
}

// fc2 (128->25), final output.
__global__ void fc2_kernel(const float* __restrict__ w, const float* __restrict__ bias,
                           float* __restrict__ out) {
    const int b = blockIdx.x, o = threadIdx.x;
    if (o < 25) {
        const float* h  = &g_h[b * 128];
        const float* wr = &w[o * 128];
        float acc = 0.0f;
        #pragma unroll
        for (int i = 0; i < 128; i++) acc += h[i] * wr[i];
        out[b * 25 + o] = acc + bias[o];
    }
}

// ---------------------------------------------------------------------------
// Launch
// ---------------------------------------------------------------------------
extern "C" void kernel_launch(void* const* d_in, const int* in_sizes, int n_in,
                              void* d_out, int out_size) {
    (void)in_sizes; (void)n_in; (void)out_size;
    const float* pc    = (const float*)d_in[0];
    const float* w1    = (const float*)d_in[1];
    const float* b1    = (const float*)d_in[2];
    const float* g1    = (const float*)d_in[3];
    const float* be1   = (const float*)d_in[4];
    const float* w2    = (const float*)d_in[5];
    const float* b2    = (const float*)d_in[6];
    const float* g2    = (const float*)d_in[7];
    const float* be2   = (const float*)d_in[8];
    const float* w3    = (const float*)d_in[9];
    const float* b3    = (const float*)d_in[10];
    const float* g3    = (const float*)d_in[11];
    const float* be3   = (const float*)d_in[12];
    const float* fc1w  = (const float*)d_in[13];
    const float* fc1b  = (const float*)d_in[14];
    const float* bn1g  = (const float*)d_in[15];
    const float* bn1b  = (const float*)d_in[16];
    const float* fc2w  = (const float*)d_in[17];
    const float* fc2b  = (const float*)d_in[18];
    float* out = (float*)d_out;

    fps_bq_kernel<<<FPS_G, FPS_T>>>(pc);
    layer1_kernel<<<8, 1024>>>(w1, b1, g1, be1);
    layer2_kernel<<<8, 1024>>>(w2, b2, g2, be2);
    layer3_kernel<<<16, 1024>>>(w3, b3, g3, be3);
    fc1_kernel<<<128, 128>>>(fc1w, fc1b, bn1g, bn1b);
    fc2_kernel<<<128, 32>>>(fc2w, fc2b, out);
}

// round 10
// speedup vs baseline: 6.5721x; 1.0296x over previous
#include <cuda_runtime.h>
#include <cuda_bf16.h>
#include <climits>

// ---------------------------------------------------------------------------
// Problem constants
// ---------------------------------------------------------------------------
constexpr int BATCH  = 128;
constexpr int NPTS   = 65536;
constexpr int NPT    = 10;     // NPOINT
constexpr int NS     = 8;      // NSAMPLE
constexpr int NPOS   = BATCH * NPT * NS;  // 10240 positions

constexpr int FPS_T  = 1024;
constexpr int VPT    = NPTS / (4 * FPS_T);   // 16 float4 vectors per thread
constexpr int CAP    = 512;                  // per-centroid hit buffer capacity
constexpr int FPS_G  = 64;                   // CTAs; each handles 2 batches

// ---------------------------------------------------------------------------
// Device scratch (no allocations allowed)
// ---------------------------------------------------------------------------
__device__ float g_grouped[NPOS * 3];         // relative coords [b][s][k][c]
__device__ float g_act1[NPOS * 8];
__device__ float g_act2[NPOS * 8];
__device__ float g_feat[BATCH * 160];
__device__ float g_h[BATCH * 128];

// ---------------------------------------------------------------------------
// Helper: deterministic block reduction of (sum, sumsq) in double
// ---------------------------------------------------------------------------
template <int NWARP>
__device__ __forceinline__ void block_red2(double& s, double& s2, double* sm) {
    const unsigned full = 0xFFFFFFFFu;
    #pragma unroll
    for (int off = 16; off > 0; off >>= 1) {
        s  += __shfl_down_sync(full, s,  off);
        s2 += __shfl_down_sync(full, s2, off);
    }
    int w = threadIdx.x >> 5, l = threadIdx.x & 31;
    if (l == 0) { sm[w * 2] = s; sm[w * 2 + 1] = s2; }
    __syncthreads();
    if (threadIdx.x == 0) {
        double a = 0.0, b = 0.0;
        #pragma unroll
        for (int i = 0; i < NWARP; i++) { a += sm[i * 2]; b += sm[i * 2 + 1]; }
        sm[0] = a; sm[1] = b;
    }
    __syncthreads();
    s = sm[0]; s2 = sm[1];
}

// exact unfused squared distance (matches reference bit-for-bit)
__device__ __forceinline__ float sqd(float x, float y, float z,
                                     float cx, float cy, float cz) {
    float dx = __fadd_rn(x, -cx);
    float dy = __fadd_rn(y, -cy);
    float dz = __fadd_rn(z, -cz);
    return __fadd_rn(__fadd_rn(__fmul_rn(dx, dx), __fmul_rn(dy, dy)),
                     __fmul_rn(dz, dz));
}

// ---------------------------------------------------------------------------
// Fused FPS + ball-query + grouping, float4-vectorized.
// grid=64; each CTA handles batches blockIdx.x and blockIdx.x+64 so the
// concurrent working set stays L2-resident. Thread t owns points
// 4*(t + i*1024) + {0..3}; scan order is ascending in n per thread so the
// strict-> comparison keeps the FIRST maximum (reference argmax semantics).
// ---------------------------------------------------------------------------
__global__ void __launch_bounds__(FPS_T, 1) fps_bq_kernel(const float* __restrict__ pc) {
    const int t = threadIdx.x;
    const int lane = t & 31, wid = t >> 5;

    __shared__ float s_cent[NPT * 3];
    __shared__ float s_cn2[NPT];
    __shared__ float s_wval[32];
    __shared__ int   s_widx[32];
    __shared__ int   s_cnt[NPT];
    __shared__ int   s_hits[NPT][CAP];   // 20 KB

    for (int pass = 0; pass < 2; ++pass) {
        const int b = blockIdx.x + pass * FPS_G;
        const float* __restrict__ px = pc + (size_t)b * 3 * NPTS;
        const float4* __restrict__ px4 = (const float4*)px;
        const float4* __restrict__ py4 = (const float4*)(px + NPTS);
        const float4* __restrict__ pz4 = (const float4*)(px + 2 * NPTS);
        const float* __restrict__ pxs = px;
        const float* __restrict__ pys = px + NPTS;
        const float* __restrict__ pzs = px + 2 * NPTS;

        float4 distv[VPT];                   // local memory, LDL/STL.128
        #pragma unroll
        for (int i = 0; i < VPT; i++)
            distv[i] = make_float4(1e10f, 1e10f, 1e10f, 1e10f);

        if (t == 0) {
            s_cent[0] = pxs[0]; s_cent[1] = pys[0]; s_cent[2] = pzs[0];
        }
        __syncthreads();

        // --------------------- FPS (9 argmax passes) ---------------------
        for (int it = 1; it < NPT; ++it) {
            const float cx = s_cent[(it - 1) * 3];
            const float cy = s_cent[(it - 1) * 3 + 1];
            const float cz = s_cent[(it - 1) * 3 + 2];
            float bv = -1e30f;
            int   bi = 0;
            #pragma unroll 4
            for (int i = 0; i < VPT; i++) {
                int v = t + i * FPS_T;
                int nb = 4 * v;
                float4 X = px4[v], Y = py4[v], Z = pz4[v];
                float4 D = distv[i];
                float d0 = fminf(D.x, sqd(X.x, Y.x, Z.x, cx, cy, cz));
                float d1 = fminf(D.y, sqd(X.y, Y.y, Z.y, cx, cy, cz));
                float d2 = fminf(D.z, sqd(X.z, Y.z, Z.z, cx, cy, cz));
                float d3 = fminf(D.w, sqd(X.w, Y.w, Z.w, cx, cy, cz));
                distv[i] = make_float4(d0, d1, d2, d3);
                if (d0 > bv) { bv = d0; bi = nb; }
                if (d1 > bv) { bv = d1; bi = nb + 1; }
                if (d2 > bv) { bv = d2; bi = nb + 2; }
                if (d3 > bv) { bv = d3; bi = nb + 3; }
            }
            // warp argmax (min-index tie-break)
            #pragma unroll
            for (int off = 16; off > 0; off >>= 1) {
                float ov = __shfl_down_sync(0xFFFFFFFFu, bv, off);
                int   oi = __shfl_down_sync(0xFFFFFFFFu, bi, off);
                if (ov > bv || (ov == bv && oi < bi)) { bv = ov; bi = oi; }
            }
            if (lane == 0) { s_wval[wid] = bv; s_widx[wid] = bi; }
            __syncthreads();
            if (t < 32) {
                bv = s_wval[t]; bi = s_widx[t];
                #pragma unroll
                for (int off = 16; off > 0; off >>= 1) {
                    float ov = __shfl_down_sync(0xFFFFFFFFu, bv, off);
                    int   oi = __shfl_down_sync(0xFFFFFFFFu, bi, off);
                    if (ov > bv || (ov == bv && oi < bi)) { bv = ov; bi = oi; }
                }
                if (t == 0) {
                    s_cent[it * 3]     = pxs[bi];
                    s_cent[it * 3 + 1] = pys[bi];
                    s_cent[it * 3 + 2] = pzs[bi];
                }
            }
            __syncthreads();
        }

        // --------------------- ball query pass ---------------------
        if (t < NPT) {
            float cx = s_cent[t * 3], cy = s_cent[t * 3 + 1], cz = s_cent[t * 3 + 2];
            s_cn2[t] = __fadd_rn(__fadd_rn(__fmul_rn(cx, cx), __fmul_rn(cy, cy)),
                                 __fmul_rn(cz, cz));
            s_cnt[t] = 0;
        }
        __syncthreads();

        const float R2 = 0.04f;
        for (int i = 0; i < VPT; i++) {
            int v = t + i * FPS_T;
            int nb = 4 * v;
            float4 X = px4[v], Y = py4[v], Z = pz4[v];
            float xs[4] = {X.x, X.y, X.z, X.w};
            float ys[4] = {Y.x, Y.y, Y.z, Y.w};
            float zs[4] = {Z.x, Z.y, Z.z, Z.w};
            #pragma unroll
            for (int j = 0; j < 4; j++) {
                float x = xs[j], y = ys[j], z = zs[j];
                float pn2 = __fadd_rn(__fadd_rn(__fmul_rn(x, x), __fmul_rn(y, y)),
                                      __fmul_rn(z, z));
                #pragma unroll
                for (int c = 0; c < NPT; c++) {
                    float cx = s_cent[c * 3], cy = s_cent[c * 3 + 1], cz = s_cent[c * 3 + 2];
                    float dot = __fadd_rn(__fadd_rn(__fmul_rn(cx, x), __fmul_rn(cy, y)),
                                          __fmul_rn(cz, z));
                    float sq  = __fadd_rn(__fadd_rn(s_cn2[c], pn2), -__fmul_rn(2.0f, dot));
                    if (sq <= R2) {
                        int p = atomicAdd(&s_cnt[c], 1);
                        if (p < CAP) s_hits[c][p] = nb + j;
                    }
                }
            }
        }
        __syncthreads();

        // -------- select 8 smallest indices per centroid (one warp each) --------
        if (wid < NPT) {
            const int c = wid;
            int cnt = s_cnt[c]; if (cnt > CAP) cnt = CAP;
            int mysel = INT_MAX;   // index chosen at selection step k == lane
            int first = INT_MAX;
            for (int k = 0; k < NS; k++) {
                int mymin = INT_MAX, mypos = -1;
                for (int j = lane; j < cnt; j += 32) {
                    int vv = s_hits[c][j];
                    if (vv < mymin) { mymin = vv; mypos = j; }
                }
                #pragma unroll
                for (int off = 16; off > 0; off >>= 1) {
                    int ov = __shfl_down_sync(0xFFFFFFFFu, mymin, off);
                    int op = __shfl_down_sync(0xFFFFFFFFu, mypos, off);
                    if (ov < mymin) { mymin = ov; mypos = op; }
                }
                mymin = __shfl_sync(0xFFFFFFFFu, mymin, 0);
                mypos = __shfl_sync(0xFFFFFFFFu, mypos, 0);
                if (k == 0) first = mymin;
                if (lane == k) mysel = mymin;
                if (lane == 0 && mymin != INT_MAX) s_hits[c][mypos] = INT_MAX;
                __syncwarp();
            }
            if (lane < NS) {
                int n = (mysel == INT_MAX) ? first : mysel;   // pad with first hit
                const float cx = s_cent[c * 3], cy = s_cent[c * 3 + 1], cz = s_cent[c * 3 + 2];
                float* o = &g_grouped[((b * NPT + c) * NS + lane) * 3];
                o[0] = __fadd_rn(pxs[n], -cx);
                o[1] = __fadd_rn(pys[n], -cy);
                o[2] = __fadd_rn(pzs[n], -cz);
            }
        }
        __syncthreads();   // protect shared buffers before next batch pass
    }
}

// ---------------------------------------------------------------------------
// Tail (unchanged, verified): one CTA per channel/feature.
// ---------------------------------------------------------------------------
__global__ void __launch_bounds__(1024) layer1_kernel(
    const float* __restrict__ w, const float* __restrict__ bias,
    const float* __restrict__ g, const float* __restrict__ be) {
    const int c = blockIdx.x, t = threadIdx.x;
    const float w0 = w[c * 3], w1 = w[c * 3 + 1], w2 = w[c * 3 + 2], bb = bias[c];
    float z[10];
    float sf = 0.0f, s2f = 0.0f;
    #pragma unroll
    for (int i = 0; i < 10; i++) {
        int pos = t + i * 1024;
        const float* x = &g_grouped[pos * 3];
        float zz = w0 * x[0] + w1 * x[1] + w2 * x[2] + bb;
        z[i] = zz; sf += zz; s2f += zz * zz;
    }
    double s = sf, s2 = s2f;
    __shared__ double red[64];
    block_red2<32>(s, s2, red);
    __shared__ float s_sc, s_sh;
    if (t == 0) {
        double mean = s / NPOS;
        double var  = s2 / NPOS - mean * mean;
        float inv = rsqrtf((float)var + 1e-5f) * g[c];
        s_sc = inv; s_sh = be[c] - (float)mean * inv;
    }
    __syncthreads();
    const float sc = s_sc, sh = s_sh;
    #pragma unroll
    for (int i = 0; i < 10; i++) {
        int pos = t + i * 1024;
        g_act1[pos * 8 + c] = fmaxf(z[i] * sc + sh, 0.0f);
    }
}

__global__ void __launch_bounds__(1024) layer2_kernel(
    const float* __restrict__ w, const float* __restrict__ bias,
    const float* __restrict__ g, const float* __restrict__ be) {
    const int c = blockIdx.x, t = threadIdx.x;
    float wr[8];
    #pragma unroll
    for (int j = 0; j < 8; j++) wr[j] = w[c * 8 + j];
    const float bb = bias[c];
    float z[10];
    float sf = 0.0f, s2f = 0.0f;
    #pragma unroll
    for (int i = 0; i < 10; i++) {
        int pos = t + i * 1024;
        const float* a = &g_act1[pos * 8];
        float zz = bb;
        #pragma unroll
        for (int j = 0; j < 8; j++) zz += wr[j] * a[j];
        z[i] = zz; sf += zz; s2f += zz * zz;
    }
    double s = sf, s2 = s2f;
    __shared__ double red[64];
    block_red2<32>(s, s2, red);
    __shared__ float s_sc, s_sh;
    if (t == 0) {
        double mean = s / NPOS;
        double var  = s2 / NPOS - mean * mean;
        float inv = rsqrtf((float)var + 1e-5f) * g[c];
        s_sc = inv; s_sh = be[c] - (float)mean * inv;
    }
    __syncthreads();
    const float sc = s_sc, sh = s_sh;
    #pragma unroll
    for (int i = 0; i < 10; i++) {
        int pos = t + i * 1024;
        g_act2[pos * 8 + c] = fmaxf(z[i] * sc + sh, 0.0f);
    }
}

__global__ void __launch_bounds__(1024) layer3_kernel(
    const float* __restrict__ w, const float* __restrict__ bias,
    const float* __restrict__ g, const float* __restrict__ be) {
    const int c = blockIdx.x, t = threadIdx.x;
    float wr[8];
    #pragma unroll
    for (int j = 0; j < 8; j++) wr[j] = w[c * 8 + j];
    const float bb = bias[c];
    float z[10];
    float sf = 0.0f, s2f = 0.0f;
    #pragma unroll
    for (int i = 0; i < 10; i++) {
        int pos = t + i * 1024;
        const float* a = &g_act2[pos * 8];
        float zz = bb;
        #pragma unroll
        for (int j = 0; j < 8; j++) zz += wr[j] * a[j];
        z[i] = zz; sf += zz; s2f += zz * zz;
    }
    double s = sf, s2 = s2f;
    __shared__ double red[64];
    block_red2<32>(s, s2, red);
    __shared__ float s_sc, s_sh;
    if (t == 0) {
        double mean = s / NPOS;
        double var  = s2 / NPOS - mean * mean;
        float inv = rsqrtf((float)var + 1e-5f) * g[c];
        s_sc = inv; s_sh = be[c] - (float)mean * inv;
    }
    __syncthreads();
    const float sc = s_sc, sh = s_sh;
    __shared__ float sa[NPOS];  // 40 KB
    #pragma unroll
    for (int i = 0; i < 10; i++) {
        int pos = t + i * 1024;
        sa[pos] = fmaxf(z[i] * sc + sh, 0.0f);
    }
    __syncthreads();
    for (int gidx = t; gidx < BATCH * NPT; gidx += 1024) {
        float m = sa[gidx * 8];
        #pragma unroll
        for (int k = 1; k < 8; k++) m = fmaxf(m, sa[gidx * 8 + k]);
        int b = gidx / NPT, ss = gidx % NPT;
        g_feat[b * 160 + c * 10 + ss] = m;
    }
}

__global__ void __launch_bounds__(128) fc1_kernel(
    const float* __restrict__ w, const float* __restrict__ bias,
    const float* __restrict__ g, const float* __restrict__ be) {
    const int o = blockIdx.x, b = threadIdx.x;
    const float* wr = &w[o * 160];
    const float* f  = &g_feat[b * 160];
    float acc = 0.0f;
    #pragma unroll
    for (int i = 0; i < 160; i++) acc += wr[i] * f[i];
    const float h = acc + bias[o];

    double s = h, s2 = (double)h * h;
    __shared__ double red[8];
    block_red2<4>(s, s2, red);
    __shared__ float s_sc, s_sh;
    if (b == 0) {
        double mean = s / BATCH;
        double var  = s2 / BATCH - mean * mean;
        float inv = rsqrtf((float)var + 1e-5f) * g[o];
        s_sc = inv; s_sh = be[o] - (float)mean * inv;
    }
    __syncthreads();
    g_h[b * 128 + o] = fmaxf(h * s_sc + s_sh, 0.0f);
}

__global__ void fc2_kernel(const float* __restrict__ w, const float* __restrict__ bias,
                           float* __restrict__ out) {
    const int b = blockIdx.x, o = threadIdx.x;
    if (o < 25) {
        const float* h  = &g_h[b * 128];
        const float* wr = &w[o * 128];
        float acc = 0.0f;
        #pragma unroll
        for (int i = 0; i < 128; i++) acc += h[i] * wr[i];
        out[b * 25 + o] = acc + bias[o];
    }
}

// ---------------------------------------------------------------------------
// Launch
// ---------------------------------------------------------------------------
extern "C" void kernel_launch(void* const* d_in, const int* in_sizes, int n_in,
                              void* d_out, int out_size) {
    (void)in_sizes; (void)n_in; (void)out_size;
    const float* pc    = (const float*)d_in[0];
    const float* w1    = (const float*)d_in[1];
    const float* b1    = (const float*)d_in[2];
    const float* g1    = (const float*)d_in[3];
    const float* be1   = (const float*)d_in[4];
    const float* w2    = (const float*)d_in[5];
    const float* b2    = (const float*)d_in[6];
    const float* g2    = (const float*)d_in[7];
    const float* be2   = (const float*)d_in[8];
    const float* w3    = (const float*)d_in[9];
    const float* b3    = (const float*)d_in[10];
    const float* g3    = (const float*)d_in[11];
    const float* be3   = (const float*)d_in[12];
    const float* fc1w  = (const float*)d_in[13];
    const float* fc1b  = (const float*)d_in[14];
    const float* bn1g  = (const float*)d_in[15];
    const float* bn1b  = (const float*)d_in[16];
    const float* fc2w  = (const float*)d_in[17];
    const float* fc2b  = (const float*)d_in[18];
    float* out = (float*)d_out;

    fps_bq_kernel<<<FPS_G, FPS_T>>>(pc);
    layer1_kernel<<<8, 1024>>>(w1, b1, g1, be1);
    layer2_kernel<<<8, 1024>>>(w2, b2, g2, be2);
    layer3_kernel<<<16, 1024>>>(w3, b3, g3, be3);
    fc1_kernel<<<128, 128>>>(fc1w, fc1b, bn1g, bn1b);
    fc2_kernel<<<128, 32>>>(fc2w, fc2b, out);
}